// round 2
// baseline (speedup 1.0000x reference)
#include <cuda_runtime.h>
#include <cstdint>

#define BATCH 16
#define NPT 2048
#define DIM 64
#define NMAT 32   // 2 * BATCH  (0..15 = x/gts, 16..31 = z)

// Scratch (allocation-free rule: __device__ globals)
// g_D now holds SQUARED distances (clamped >= 0). sqrt applied only in loss.
__device__ float g_D[(size_t)NMAT * NPT * NPT];   // 512 MB
__device__ float g_sq[NMAT * NPT];                // squared norms
__device__ int2  g_edges[NMAT * (NPT - 1)];       // MST edges (src, dst)
__device__ float g_partial[NMAT];

// ---------------------------------------------------------------------------
// 1. squared norms
// ---------------------------------------------------------------------------
__global__ void norms_kernel(const float* __restrict__ gts, const float* __restrict__ z) {
    int row = blockIdx.x * blockDim.x + threadIdx.x;
    if (row >= NMAT * NPT) return;
    const float* P = (row < BATCH * NPT) ? gts : z;
    int r = (row < BATCH * NPT) ? row : row - BATCH * NPT;
    const float4* p = (const float4*)(P + (size_t)r * DIM);
    float s = 0.f;
#pragma unroll
    for (int k = 0; k < DIM / 4; k++) {
        float4 v = p[k];
        s += v.x * v.x + v.y * v.y + v.z * v.z + v.w * v.w;
    }
    g_sq[row] = s;
}

// ---------------------------------------------------------------------------
// 2. squared-distance matrices: D2 = max(sq_i + sq_j - 2*dot, 0)   (NO sqrt)
//    128x128 tile per block, 256 threads, 8x8 per thread, K staged by 16.
//    Symmetric: only bj >= bi blocks compute; off-diagonal blocks also store
//    the transposed tile (32B-sector-aligned float4 stores).
// ---------------------------------------------------------------------------
#define KS 16
__global__ void __launch_bounds__(256) dist_kernel(const float* __restrict__ gts,
                                                   const float* __restrict__ z) {
    int bi = blockIdx.y, bj = blockIdx.x;
    if (bj < bi) return;
    int bm = blockIdx.z;
    const float* P = (bm < BATCH) ? gts + (size_t)bm * NPT * DIM
                                  : z + (size_t)(bm - BATCH) * NPT * DIM;
    int i0 = bi * 128, j0 = bj * 128;
    int tid = threadIdx.x;
    int tx = tid & 15;   // j sub-tile
    int ty = tid >> 4;   // i sub-tile

    __shared__ float As[KS][132];  // [k][i], stride 132 keeps float4 alignment
    __shared__ float Bs[KS][132];

    float acc[8][8] = {};

    for (int ks = 0; ks < DIM; ks += KS) {
        __syncthreads();
        // 128 rows x 16 k = 512 float4 loads; 2 per thread per tile
#pragma unroll
        for (int t = 0; t < 2; t++) {
            int idx = tid + t * 256;       // 0..511
            int i = idx >> 2;              // row 0..127
            int kk = (idx & 3) * 4;        // 0,4,8,12
            float4 va = *(const float4*)(P + (size_t)(i0 + i) * DIM + ks + kk);
            As[kk + 0][i] = va.x; As[kk + 1][i] = va.y;
            As[kk + 2][i] = va.z; As[kk + 3][i] = va.w;
            float4 vb = *(const float4*)(P + (size_t)(j0 + i) * DIM + ks + kk);
            Bs[kk + 0][i] = vb.x; Bs[kk + 1][i] = vb.y;
            Bs[kk + 2][i] = vb.z; Bs[kk + 3][i] = vb.w;
        }
        __syncthreads();
#pragma unroll
        for (int k = 0; k < KS; k++) {
            float a[8], b[8];
            *(float4*)(a)     = *(const float4*)&As[k][ty * 8];
            *(float4*)(a + 4) = *(const float4*)&As[k][ty * 8 + 4];
            *(float4*)(b)     = *(const float4*)&Bs[k][tx * 8];
            *(float4*)(b + 4) = *(const float4*)&Bs[k][tx * 8 + 4];
#pragma unroll
            for (int r = 0; r < 8; r++)
#pragma unroll
                for (int c = 0; c < 8; c++)
                    acc[r][c] += a[r] * b[c];
        }
    }

    const float* sqb = g_sq + bm * NPT;
    float sqi[8], sqj[8];
#pragma unroll
    for (int r = 0; r < 8; r++) sqi[r] = sqb[i0 + ty * 8 + r];
#pragma unroll
    for (int c = 0; c < 8; c++) sqj[c] = sqb[j0 + tx * 8 + c];

    // overwrite acc with clamped squared distances
#pragma unroll
    for (int r = 0; r < 8; r++)
#pragma unroll
        for (int c = 0; c < 8; c++)
            acc[r][c] = fmaxf(sqi[r] + sqj[c] - 2.f * acc[r][c], 0.f);

    float* Dm = g_D + (size_t)bm * NPT * NPT;
    // direct store (i, j)
#pragma unroll
    for (int r = 0; r < 8; r++) {
        int gi = i0 + ty * 8 + r;
        float4 o0 = {acc[r][0], acc[r][1], acc[r][2], acc[r][3]};
        float4 o1 = {acc[r][4], acc[r][5], acc[r][6], acc[r][7]};
        *(float4*)&Dm[(size_t)gi * NPT + j0 + tx * 8]     = o0;
        *(float4*)&Dm[(size_t)gi * NPT + j0 + tx * 8 + 4] = o1;
    }
    // transposed store (j, i) for off-diagonal blocks
    if (bi != bj) {
#pragma unroll
        for (int c = 0; c < 8; c++) {
            int gj = j0 + tx * 8 + c;
            float4 o0 = {acc[0][c], acc[1][c], acc[2][c], acc[3][c]};
            float4 o1 = {acc[4][c], acc[5][c], acc[6][c], acc[7][c]};
            *(float4*)&Dm[(size_t)gj * NPT + i0 + ty * 8]     = o0;
            *(float4*)&Dm[(size_t)gj * NPT + i0 + ty * 8 + 4] = o1;
        }
    }
}

// ---------------------------------------------------------------------------
// 3. Prim's MST on squared distances. One block of 256 threads per instance.
//    Keys live in REGISTERS: thread t owns nodes [t*8, t*8+8).
//    key = (d2_bits << 22) | (src << 11) | idx  -> u64 min == argmin by d2,
//    winner carries its edge. Relax uses strict d2_bits comparison (matches
//    reference's strict < on distance). ONE __syncthreads per step; per-warp
//    minima double-buffered by step parity; every thread redundantly reduces
//    the 8 warp minima (broadcast smem loads), so no second barrier.
// ---------------------------------------------------------------------------
static __device__ __forceinline__ unsigned long long umin64(unsigned long long a,
                                                            unsigned long long b) {
    return a < b ? a : b;
}

__global__ void __launch_bounds__(256) prim_kernel() {
    __shared__ unsigned long long wmin[2][8];

    const unsigned long long VIS = ~0ull;
    int bm = blockIdx.x;
    int tid = threadIdx.x;
    int lane = tid & 31;
    int wid = tid >> 5;
    int base = tid * 8;
    const float* Dm = g_D + (size_t)bm * NPT * NPT;

    // init from row 0 (src = 0 for all)
    unsigned long long key[8];
    {
        float4 a = *(const float4*)(Dm + base);
        float4 b = *(const float4*)(Dm + base + 4);
        float d[8] = {a.x, a.y, a.z, a.w, b.x, b.y, b.z, b.w};
#pragma unroll
        for (int q = 0; q < 8; q++)
            key[q] = ((unsigned long long)__float_as_uint(d[q]) << 22) | (unsigned)(base + q);
    }
    if (tid == 0) key[0] = VIS;

    unsigned long long lmin = key[0];
#pragma unroll
    for (int q = 1; q < 8; q++) lmin = umin64(lmin, key[q]);
#pragma unroll
    for (int o = 16; o; o >>= 1)
        lmin = umin64(lmin, __shfl_down_sync(0xFFFFFFFFu, lmin, o));
    if (lane == 0) wmin[0][wid] = lmin;

    int2* ed = g_edges + bm * (NPT - 1);
    int par = 0;

    for (int step = 0; step < NPT - 1; step++) {
        __syncthreads();
        // all threads redundantly find the global winner (broadcast loads)
        unsigned long long w = wmin[par][0];
#pragma unroll
        for (int q = 1; q < 8; q++) w = umin64(w, wmin[par][q]);
        int j = (int)(w & 0x7FFu);
        if (tid == 0)
            ed[step] = make_int2((int)((w >> 11) & 0x7FFu), j);

        // relax with row j (issue loads immediately)
        const float* row = Dm + (size_t)j * NPT;
        float4 a = *(const float4*)(row + base);
        float4 b = *(const float4*)(row + base + 4);
        float dd[8] = {a.x, a.y, a.z, a.w, b.x, b.y, b.z, b.w};

        if ((j >> 3) == tid) key[j & 7] = VIS;

        unsigned long long lm = VIS;
#pragma unroll
        for (int q = 0; q < 8; q++) {
            unsigned long long k = key[q];
            if (k != VIS) {
                unsigned nd = __float_as_uint(dd[q]);
                if (nd < (unsigned)(k >> 22)) {   // strict < on d2, like reference
                    k = ((unsigned long long)nd << 22) |
                        ((unsigned long long)(unsigned)j << 11) | (unsigned)(base + q);
                    key[q] = k;
                }
            }
            lm = umin64(lm, k);
        }
#pragma unroll
        for (int o = 16; o; o >>= 1)
            lm = umin64(lm, __shfl_down_sync(0xFFFFFFFFu, lm, o));
        if (lane == 0) wmin[par ^ 1][wid] = lm;
        par ^= 1;
    }
}

// ---------------------------------------------------------------------------
// 4. loss: 0.5 * sum over all MST edges of (sqrt(D2x[p]) - sqrt(D2z[p]))^2
// ---------------------------------------------------------------------------
__global__ void loss_kernel() {
    int bm = blockIdx.x;
    int b = bm & (BATCH - 1);
    const int2* ed = g_edges + bm * (NPT - 1);
    const float* Dx = g_D + (size_t)b * NPT * NPT;
    const float* Dz = g_D + (size_t)(BATCH + b) * NPT * NPT;

    float acc = 0.f;
    for (int e = threadIdx.x; e < NPT - 1; e += 256) {
        int2 p = ed[e];
        float dx = sqrtf(Dx[(size_t)p.x * NPT + p.y]);
        float dz = sqrtf(Dz[(size_t)p.x * NPT + p.y]);
        float t = dx - dz;
        acc += t * t;
    }
    __shared__ float sm[256];
    sm[threadIdx.x] = acc;
    __syncthreads();
    for (int s = 128; s; s >>= 1) {
        if (threadIdx.x < s) sm[threadIdx.x] += sm[threadIdx.x + s];
        __syncthreads();
    }
    if (threadIdx.x == 0) g_partial[bm] = sm[0];
}

__global__ void final_kernel(float* out) {
    if (threadIdx.x == 0) {
        float s = 0.f;
        for (int i = 0; i < NMAT; i++) s += g_partial[i];
        out[0] = 0.5f * s;
    }
}

// ---------------------------------------------------------------------------
extern "C" void kernel_launch(void* const* d_in, const int* in_sizes, int n_in,
                              void* d_out, int out_size) {
    (void)in_sizes; (void)n_in; (void)out_size;
    const float* gts = (const float*)d_in[0];
    const float* z   = (const float*)d_in[1];

    norms_kernel<<<(NMAT * NPT + 255) / 256, 256>>>(gts, z);

    dim3 g(NPT / 128, NPT / 128, NMAT);
    dist_kernel<<<g, 256>>>(gts, z);

    prim_kernel<<<NMAT, 256>>>();

    loss_kernel<<<NMAT, 256>>>();
    final_kernel<<<1, 32>>>((float*)d_out);
}